// round 5
// baseline (speedup 1.0000x reference)
#include <cuda_runtime.h>
#include <cuda_fp16.h>
#include <math.h>
#include <stdint.h>

// Problem constants
static constexpr int Bc   = 8;
static constexpr int Nn   = 10000;
static constexpr int Ee   = 320000;
static constexpr int HISTc = 24;
static constexpr int PREDc = 12;
static constexpr int TT   = HISTc + PREDc;   // 36
static constexpr int HIDc = 64;

// ---------------- device scratch (static, no allocations) ----------------
__device__ __align__(16) __half d_hbuf_t[(long long)Bc * Ee * 32]; // messages, tgt-sorted
__device__ __align__(16) __half d_hbuf_s[(long long)Bc * Ee * 32]; // messages, src-sorted
__device__ __align__(16) float d_h[Bc * Nn * HIDc];   // GRU hidden state
__device__ float d_xn[Bc * Nn];         // current node scalar
__device__ float d_ea[Ee];              // normalized edge attr (original order)
__device__ float d_stats[2];
__device__ int d_deg_t[Nn], d_deg_s[Nn];
__device__ int d_off_t[Nn + 1], d_off_s[Nn + 1];
__device__ int d_cnt_t[Nn], d_cnt_s[Nn];
__device__ int d_sslot_t[Ee];           // t-order slot -> s-order slot
__device__ int d_src_t[Ee], d_tgt_t[Ee];// node ids in t-order
__device__ float d_ea_t[Ee];            // edge attr in t-order
__device__ __align__(16) float2 d_wihT2[30 * 96];  // paired GRU input weights
__device__ __align__(16) float2 d_whhT2[64 * 96];  // paired GRU hidden weights

// ---------------- helpers ----------------
__device__ __forceinline__ float sigm(float x) {
    return __fdividef(1.0f, 1.0f + __expf(-x));
}
__device__ __forceinline__ float tanh_f(float x) {
    x = fminf(15.0f, fmaxf(-15.0f, x));
    float e = __expf(-2.0f * x);
    return __fdividef(1.0f - e, 1.0f + e);
}
__device__ __forceinline__ unsigned long long splat2(float x) {
    unsigned long long r;
    asm("mov.b64 %0, {%1, %1};" : "=l"(r) : "f"(x));
    return r;
}
__device__ __forceinline__ unsigned long long pack2(float lo, float hi) {
    unsigned long long r;
    asm("mov.b64 %0, {%1, %2};" : "=l"(r) : "f"(lo), "f"(hi));
    return r;
}
__device__ __forceinline__ void fma2(unsigned long long& d, unsigned long long a, unsigned long long b) {
    asm("fma.rn.f32x2 %0, %1, %2, %0;" : "+l"(d) : "l"(a), "l"(b));
}
__device__ __forceinline__ float2 unpack2(unsigned long long v) {
    float2 f;
    asm("mov.b64 {%0, %1}, %2;" : "=f"(f.x), "=f"(f.y) : "l"(v));
    return f;
}

// ---------------- setup kernels ----------------
__global__ void k1_zero_init(const float* __restrict__ t2m) {
    int i = blockIdx.x * blockDim.x + threadIdx.x;
    if (i < 2) d_stats[i] = 0.f;
    if (i < Nn) { d_deg_t[i] = 0; d_deg_s[i] = 0; d_cnt_t[i] = 0; d_cnt_s[i] = 0; }
    if (i < Bc * Nn) {
        int b = i / Nn, n = i - b * Nn;
        d_xn[i] = t2m[((long long)b * HISTc + (HISTc - 1)) * Nn + n];
    }
    for (long long j = i; j < (long long)Bc * Nn * HIDc; j += (long long)gridDim.x * blockDim.x)
        d_h[j] = 0.f;
}

__global__ void k2_stats_deg(const float* __restrict__ ea, const int* __restrict__ ei) {
    __shared__ float ssum[256], ssq[256];
    int t = threadIdx.x;
    int i = blockIdx.x * 256 + t;
    float v = 0.f;
    if (i < Ee) {
        v = ea[i];
        atomicAdd(&d_deg_s[ei[i]], 1);
        atomicAdd(&d_deg_t[ei[Ee + i]], 1);
    }
    ssum[t] = v; ssq[t] = v * v;
    __syncthreads();
    for (int s = 128; s > 0; s >>= 1) {
        if (t < s) { ssum[t] += ssum[t + s]; ssq[t] += ssq[t + s]; }
        __syncthreads();
    }
    if (t == 0) {
        atomicAdd(&d_stats[0], ssum[0]);
        atomicAdd(&d_stats[1], ssq[0]);
    }
}

__global__ void k3_norm_scan(const float* __restrict__ ea) {
    if (blockIdx.x < 2) {
        int which = blockIdx.x;
        const int* deg = which ? d_deg_s : d_deg_t;
        int* off = which ? d_off_s : d_off_t;
        __shared__ int part[256];
        const int CH = (Nn + 255) / 256;
        int t = threadIdx.x;
        int s = 0;
        for (int i = 0; i < CH; i++) {
            int idx = t * CH + i;
            if (idx < Nn) s += deg[idx];
        }
        part[t] = s;
        __syncthreads();
        if (t == 0) {
            int run = 0;
            for (int i = 0; i < 256; i++) { int vv = part[i]; part[i] = run; run += vv; }
            off[Nn] = run;
        }
        __syncthreads();
        int run = part[t];
        for (int i = 0; i < CH; i++) {
            int idx = t * CH + i;
            if (idx < Nn) { off[idx] = run; run += deg[idx]; }
        }
        return;
    }
    int i = (blockIdx.x - 2) * blockDim.x + threadIdx.x;
    if (i >= Ee) return;
    float s = d_stats[0], sq = d_stats[1];
    float mean = s / (float)Ee;
    float var = (sq - s * s / (float)Ee) / (float)(Ee - 1);
    float inv = rsqrtf(var);
    d_ea[i] = (ea[i] - mean) * inv;
}

__global__ void k4_fill(const int* __restrict__ ei) {
    int e = blockIdx.x * blockDim.x + threadIdx.x;
    if (e >= Ee) return;
    int sn = ei[e], tn = ei[Ee + e];
    int ps = atomicAdd(&d_cnt_s[sn], 1);
    int sslot = d_off_s[sn] + ps;
    int pt = atomicAdd(&d_cnt_t[tn], 1);
    int tslot = d_off_t[tn] + pt;
    d_sslot_t[tslot] = sslot;
    d_src_t[tslot] = sn;
    d_tgt_t[tslot] = tn;
    d_ea_t[tslot] = d_ea[e];
}

__global__ void k5_pack_weights(const float* __restrict__ wih, const float* __restrict__ whh) {
    int i = blockIdx.x * blockDim.x + threadIdx.x;
    if (i < 30 * 96) {
        int k = i / 96, c = i - k * 96;
        int g = c / 32, j = c - g * 32;
        d_wihT2[i] = make_float2(wih[(g * 64 + j) * 30 + k], wih[(g * 64 + 32 + j) * 30 + k]);
    }
    if (i < 64 * 96) {
        int k = i / 96, c = i - k * 96;
        int g = c / 32, j = c - g * 32;
        d_whhT2[i] = make_float2(whh[(g * 64 + j) * 64 + k], whh[(g * 64 + 32 + j) * 64 + k]);
    }
}

// ---------------- edge MLP kernel (FFMA2 + LDS.128 weights, fp16 dual output) ----------------
__global__ void __launch_bounds__(128) edge_kernel(
    const float* __restrict__ feat,
    const float* __restrict__ w1, const float* __restrict__ b1,
    const float* __restrict__ w2, const float* __restrict__ b2, int t)
{
    __shared__ __align__(16) float s_w1[35 * 32];
    __shared__ __align__(16) float s_b1[32];
    __shared__ __align__(16) float s_w2p[32 * 32];   // padded: 30 real + 2 zero per row
    __shared__ __align__(16) float s_b2[32];
    for (int i = threadIdx.x; i < 35 * 32; i += 128) s_w1[i] = w1[i];
    for (int i = threadIdx.x; i < 32 * 32; i += 128) {
        int k = i >> 5, j = i & 31;
        s_w2p[i] = (j < 30) ? w2[k * 30 + j] : 0.f;
    }
    if (threadIdx.x < 32) {
        s_b1[threadIdx.x] = b1[threadIdx.x];
        s_b2[threadIdx.x] = (threadIdx.x < 30) ? b2[threadIdx.x] : 0.f;
    }
    __syncthreads();

    int idx = blockIdx.x * 128 + threadIdx.x;
    int b = blockIdx.y;
    int sn = d_src_t[idx], tn = d_tgt_t[idx];
    int ss = d_sslot_t[idx];

    float in[35];
    in[0] = d_xn[b * Nn + sn];
    {
        const float4* fs = (const float4*)(feat + ((long long)(b * TT + HISTc + t) * Nn + sn) * 16);
        float4 f0 = fs[0], f1 = fs[1], f2 = fs[2], f3 = fs[3];
        in[1] = f0.x; in[2] = f0.y; in[3] = f0.z; in[4] = f0.w;
        in[5] = f1.x; in[6] = f1.y; in[7] = f1.z; in[8] = f1.w;
        in[9] = f2.x; in[10] = f2.y; in[11] = f2.z; in[12] = f2.w;
        in[13] = f3.x; in[14] = f3.y; in[15] = f3.z; in[16] = f3.w;
    }
    in[17] = d_xn[b * Nn + tn];
    {
        const float4* fs = (const float4*)(feat + ((long long)(b * TT + HISTc + t) * Nn + tn) * 16);
        float4 f0 = fs[0], f1 = fs[1], f2 = fs[2], f3 = fs[3];
        in[18] = f0.x; in[19] = f0.y; in[20] = f0.z; in[21] = f0.w;
        in[22] = f1.x; in[23] = f1.y; in[24] = f1.z; in[25] = f1.w;
        in[26] = f2.x; in[27] = f2.y; in[28] = f2.z; in[29] = f2.w;
        in[30] = f3.x; in[31] = f3.y; in[32] = f3.z; in[33] = f3.w;
    }
    in[34] = d_ea_t[idx];

    // ---- layer 1: 35 -> 32, LDS.128 weight pairs ----
    unsigned long long acc1[16];
    {
        const unsigned long long* bp = (const unsigned long long*)s_b1;
        #pragma unroll
        for (int j = 0; j < 16; j++) acc1[j] = bp[j];
    }
    {
        const ulonglong2* wp = (const ulonglong2*)s_w1;
        #pragma unroll
        for (int k = 0; k < 35; k++) {
            unsigned long long xk = splat2(in[k]);
            #pragma unroll
            for (int j = 0; j < 8; j++) {
                ulonglong2 wv = wp[k * 8 + j];
                fma2(acc1[2 * j], xk, wv.x);
                fma2(acc1[2 * j + 1], xk, wv.y);
            }
        }
    }
    float h1[32];
    #pragma unroll
    for (int j = 0; j < 16; j++) {
        float2 f = unpack2(acc1[j]);
        h1[2 * j] = sigm(f.x);
        h1[2 * j + 1] = sigm(f.y);
    }

    // ---- layer 2: 32 -> 30 (padded to 32), LDS.128 weight pairs ----
    unsigned long long acc2[16];
    {
        const unsigned long long* bp = (const unsigned long long*)s_b2;
        #pragma unroll
        for (int j = 0; j < 16; j++) acc2[j] = bp[j];
    }
    {
        const ulonglong2* wp = (const ulonglong2*)s_w2p;
        #pragma unroll
        for (int k = 0; k < 32; k++) {
            unsigned long long xk = splat2(h1[k]);
            #pragma unroll
            for (int j = 0; j < 8; j++) {
                ulonglong2 wv = wp[k * 8 + j];
                fma2(acc2[2 * j], xk, wv.x);
                fma2(acc2[2 * j + 1], xk, wv.y);
            }
        }
    }

    // ---- sigmoid + fp16 pack (channels 30,31 forced zero) ----
    uint32_t hp[16];
    #pragma unroll
    for (int j = 0; j < 15; j++) {
        float2 f = unpack2(acc2[j]);
        __half2 h = __floats2half2_rn(sigm(f.x), sigm(f.y));
        hp[j] = *(uint32_t*)&h;
    }
    hp[15] = 0u;

    const uint4* hpv = (const uint4*)hp;
    uint4* dt = (uint4*)(d_hbuf_t + ((long long)b * Ee + idx) * 32);
    uint4* ds = (uint4*)(d_hbuf_s + ((long long)b * Ee + ss) * 32);
    #pragma unroll
    for (int q = 0; q < 4; q++) dt[q] = hpv[q];
    #pragma unroll
    for (int q = 0; q < 4; q++) ds[q] = hpv[q];
}

// ---------------- persistent step2: 4 rows per warp ----------------
static constexpr int S2_BLOCKS = 592;
static constexpr int S2_WARPS  = 8;     // 256 threads
static constexpr int TASKS = Bc * Nn / 4;  // 20000

__global__ void __launch_bounds__(256, 2) step2_kernel(
    const float* __restrict__ feat,
    const float* __restrict__ node_w, const float* __restrict__ node_b,
    const float* __restrict__ bih, const float* __restrict__ bhh,
    const float* __restrict__ fcw, const float* __restrict__ fcb,
    float* __restrict__ out, int t)
{
    extern __shared__ float dynw[];
    float2* s_wih2 = (float2*)dynw;                 // [30][96] pairs
    float2* s_whh2 = (float2*)(dynw + 30 * 96 * 2); // [64][96] pairs
    __shared__ __align__(16) float sx[S2_WARPS][4][32];   // agg per row
    __shared__ __align__(16) float sxin[S2_WARPS][4][32]; // xin per row
    __shared__ __align__(16) float sh[S2_WARPS][4 * 64];  // h per row (linear)
    __shared__ float s_nw[30 * 13], s_nb[16];

    for (int i = threadIdx.x; i < 30 * 96; i += 256) s_wih2[i] = d_wihT2[i];
    for (int i = threadIdx.x; i < 64 * 96; i += 256) s_whh2[i] = d_whhT2[i];
    for (int i = threadIdx.x; i < 30 * 13; i += 256) s_nw[i] = node_w[i];
    if (threadIdx.x < 13) s_nb[threadIdx.x] = node_b[threadIdx.x];
    __syncthreads();

    int lane = threadIdx.x & 31;
    int w = threadIdx.x >> 5;
    float* shp = sh[w];

    // hoisted per-lane constants
    unsigned long long bih_r = pack2(bih[lane],       bih[32 + lane]);
    unsigned long long bih_z = pack2(bih[64 + lane],  bih[96 + lane]);
    unsigned long long bih_n = pack2(bih[128 + lane], bih[160 + lane]);
    unsigned long long bhh_r = pack2(bhh[lane],       bhh[32 + lane]);
    unsigned long long bhh_z = pack2(bhh[64 + lane],  bhh[96 + lane]);
    unsigned long long bhh_n = pack2(bhh[128 + lane], bhh[160 + lane]);
    float fcw0 = fcw[lane], fcw1 = fcw[32 + lane];
    float fcb0 = fcb[0];

    for (int task = blockIdx.x * S2_WARPS + w; task < TASKS; task += S2_BLOCKS * S2_WARPS) {
        int row0 = task * 4;
        int b = row0 / Nn, n0 = row0 - b * Nn;   // rows row0..row0+3 share b

        // --- gather agg for 4 rows ---
        #pragma unroll
        for (int r = 0; r < 4; r++) {
            int n = n0 + r;
            float acc = 0.f;
            int e0 = d_off_t[n], e1 = d_off_t[n + 1];
            const __half* p = d_hbuf_t + ((long long)b * Ee + e0) * 32 + lane;
            int cnt = e1 - e0;
            int i = 0;
            for (; i + 4 <= cnt; i += 4) {
                float v0 = __half2float(p[(long long)(i) * 32]);
                float v1 = __half2float(p[(long long)(i + 1) * 32]);
                float v2 = __half2float(p[(long long)(i + 2) * 32]);
                float v3 = __half2float(p[(long long)(i + 3) * 32]);
                acc += (v0 + v1) + (v2 + v3);
            }
            for (; i < cnt; i++) acc += __half2float(p[(long long)i * 32]);
            e0 = d_off_s[n]; e1 = d_off_s[n + 1];
            p = d_hbuf_s + ((long long)b * Ee + e0) * 32 + lane;
            cnt = e1 - e0;
            i = 0;
            for (; i + 4 <= cnt; i += 4) {
                float v0 = __half2float(p[(long long)(i) * 32]);
                float v1 = __half2float(p[(long long)(i + 1) * 32]);
                float v2 = __half2float(p[(long long)(i + 2) * 32]);
                float v3 = __half2float(p[(long long)(i + 3) * 32]);
                acc -= (v0 + v1) + (v2 + v3);
            }
            for (; i < cnt; i++) acc -= __half2float(p[(long long)i * 32]);
            sx[w][r][lane] = acc;
        }
        __syncwarp();

        // --- node MLP: 2 rows per pass (26 active lanes), write g into sxin ---
        #pragma unroll
        for (int pass = 0; pass < 2; pass++) {
            if (lane < 26) {
                int r = 2 * pass + (lane >= 13);
                int u = (lane >= 13) ? lane - 13 : lane;
                float g = s_nb[u];
                #pragma unroll
                for (int k = 0; k < 30; k++) g = fmaf(sx[w][r][k], s_nw[k * 13 + u], g);
                sxin[w][r][u] = sigm(g);
            }
        }
        // xn + feat into sxin
        if (lane < 4) sxin[w][lane][13] = d_xn[row0 + lane];
        #pragma unroll
        for (int r = 0; r < 4; r++) {
            if (lane < 16)
                sxin[w][r][14 + lane] = feat[((long long)(b * TT + HISTc + t) * Nn + n0 + r) * 16 + lane];
        }
        // load h (256 contiguous floats) into shp
        {
            const float4* hbase = (const float4*)(d_h + (long long)row0 * 64);
            float4* shv = (float4*)shp;
            shv[lane * 2] = hbase[lane * 2];
            shv[lane * 2 + 1] = hbase[lane * 2 + 1];
        }
        __syncwarp();

        // --- GRU: 4 rows share each weight load ---
        unsigned long long ar0 = bih_r, az0 = bih_z, an0 = bih_n;
        unsigned long long ar1 = bih_r, az1 = bih_z, an1 = bih_n;
        unsigned long long ar2 = bih_r, az2 = bih_z, an2 = bih_n;
        unsigned long long ar3 = bih_r, az3 = bih_z, an3 = bih_n;
        #pragma unroll
        for (int k = 0; k < 30; k++) {
            const unsigned long long* wr = (const unsigned long long*)(s_wih2 + k * 96);
            unsigned long long wR = wr[lane], wZ = wr[32 + lane], wN = wr[64 + lane];
            unsigned long long x0 = splat2(sxin[w][0][k]);
            unsigned long long x1 = splat2(sxin[w][1][k]);
            unsigned long long x2 = splat2(sxin[w][2][k]);
            unsigned long long x3 = splat2(sxin[w][3][k]);
            fma2(ar0, x0, wR); fma2(az0, x0, wZ); fma2(an0, x0, wN);
            fma2(ar1, x1, wR); fma2(az1, x1, wZ); fma2(an1, x1, wN);
            fma2(ar2, x2, wR); fma2(az2, x2, wZ); fma2(an2, x2, wN);
            fma2(ar3, x3, wR); fma2(az3, x3, wZ); fma2(an3, x3, wN);
        }
        unsigned long long gr0 = bhh_r, gz0 = bhh_z, gn0 = bhh_n;
        unsigned long long gr1 = bhh_r, gz1 = bhh_z, gn1 = bhh_n;
        unsigned long long gr2 = bhh_r, gz2 = bhh_z, gn2 = bhh_n;
        unsigned long long gr3 = bhh_r, gz3 = bhh_z, gn3 = bhh_n;
        #pragma unroll
        for (int k = 0; k < 64; k++) {
            const unsigned long long* wr = (const unsigned long long*)(s_whh2 + k * 96);
            unsigned long long wR = wr[lane], wZ = wr[32 + lane], wN = wr[64 + lane];
            unsigned long long h0 = splat2(shp[k]);
            unsigned long long h1 = splat2(shp[64 + k]);
            unsigned long long h2 = splat2(shp[128 + k]);
            unsigned long long h3 = splat2(shp[192 + k]);
            fma2(gr0, h0, wR); fma2(gz0, h0, wZ); fma2(gn0, h0, wN);
            fma2(gr1, h1, wR); fma2(gz1, h1, wZ); fma2(gn1, h1, wN);
            fma2(gr2, h2, wR); fma2(gz2, h2, wZ); fma2(gn2, h2, wN);
            fma2(gr3, h3, wR); fma2(gz3, h3, wZ); fma2(gn3, h3, wN);
        }

        // --- per-row epilogue ---
        #pragma unroll
        for (int r = 0; r < 4; r++) {
            unsigned long long arv = (r == 0) ? ar0 : (r == 1) ? ar1 : (r == 2) ? ar2 : ar3;
            unsigned long long azv = (r == 0) ? az0 : (r == 1) ? az1 : (r == 2) ? az2 : az3;
            unsigned long long anv = (r == 0) ? an0 : (r == 1) ? an1 : (r == 2) ? an2 : an3;
            unsigned long long grv = (r == 0) ? gr0 : (r == 1) ? gr1 : (r == 2) ? gr2 : gr3;
            unsigned long long gzv = (r == 0) ? gz0 : (r == 1) ? gz1 : (r == 2) ? gz2 : gz3;
            unsigned long long gnv = (r == 0) ? gn0 : (r == 1) ? gn1 : (r == 2) ? gn2 : gn3;
            float2 fa_r = unpack2(arv), fa_z = unpack2(azv), fa_n = unpack2(anv);
            float2 fg_r = unpack2(grv), fg_z = unpack2(gzv), fg_n = unpack2(gnv);

            float hold0 = shp[r * 64 + lane];
            float hold1 = shp[r * 64 + 32 + lane];

            float r0 = sigm(fa_r.x + fg_r.x), r1 = sigm(fa_r.y + fg_r.y);
            float z0 = sigm(fa_z.x + fg_z.x), z1 = sigm(fa_z.y + fg_z.y);
            float nn0 = tanh_f(fa_n.x + r0 * fg_n.x), nn1 = tanh_f(fa_n.y + r1 * fg_n.y);
            float hn0 = (1.f - z0) * nn0 + z0 * hold0;
            float hn1 = (1.f - z1) * nn1 + z1 * hold1;

            long long rw = (long long)(row0 + r) * 64;
            d_h[rw + lane] = hn0;
            d_h[rw + 32 + lane] = hn1;

            float o = hn0 * fcw0 + hn1 * fcw1;
            #pragma unroll
            for (int off = 16; off > 0; off >>= 1)
                o += __shfl_xor_sync(0xffffffffu, o, off);
            if (lane == 0) {
                float v = o + fcb0;
                d_xn[row0 + r] = v;
                out[((long long)b * PREDc + t) * Nn + n0 + r] = v;
            }
        }
        __syncwarp();
    }
}

// ---------------- launcher ----------------
extern "C" void kernel_launch(void* const* d_in, const int* in_sizes, int n_in,
                              void* d_out, int out_size)
{
    const float* t2m  = (const float*)d_in[0];
    const float* feat = (const float*)d_in[1];
    const int*   ei   = (const int*)d_in[2];
    const float* ea   = (const float*)d_in[3];
    const float* w1   = (const float*)d_in[4];
    const float* b1   = (const float*)d_in[5];
    const float* w2   = (const float*)d_in[6];
    const float* b2   = (const float*)d_in[7];
    const float* nw   = (const float*)d_in[8];
    const float* nb   = (const float*)d_in[9];
    const float* wih  = (const float*)d_in[10];
    const float* whh  = (const float*)d_in[11];
    const float* bih  = (const float*)d_in[12];
    const float* bhh  = (const float*)d_in[13];
    const float* fcw  = (const float*)d_in[14];
    const float* fcb  = (const float*)d_in[15];
    float* out = (float*)d_out;

    const int smem2 = (30 * 96 + 64 * 96) * 2 * (int)sizeof(float);
    cudaFuncSetAttribute(step2_kernel, cudaFuncAttributeMaxDynamicSharedMemorySize, smem2);

    const int EB = (Ee + 255) / 256;

    k1_zero_init<<<(Bc * Nn + 255) / 256, 256>>>(t2m);
    k2_stats_deg<<<EB, 256>>>(ea, ei);
    k3_norm_scan<<<EB + 2, 256>>>(ea);
    k4_fill<<<EB, 256>>>(ei);
    k5_pack_weights<<<(64 * 96 + 255) / 256, 256>>>(wih, whh);

    dim3 egrid(Ee / 128, Bc);
    for (int t = 0; t < PREDc; t++) {
        edge_kernel<<<egrid, 128>>>(feat, w1, b1, w2, b2, t);
        step2_kernel<<<S2_BLOCKS, 256, smem2>>>(feat, nw, nb, bih, bhh, fcw, fcb, out, t);
    }
}

// round 6
// speedup vs baseline: 1.1475x; 1.1475x over previous
#include <cuda_runtime.h>
#include <cuda_fp16.h>
#include <math.h>
#include <stdint.h>

// Problem constants
static constexpr int Bc   = 8;
static constexpr int Nn   = 10000;
static constexpr int Ee   = 320000;
static constexpr int HISTc = 24;
static constexpr int PREDc = 12;
static constexpr int TT   = HISTc + PREDc;   // 36
static constexpr int HIDc = 64;

// ---------------- device scratch (static, no allocations) ----------------
__device__ __align__(16) __half d_hbuf_t[(long long)Bc * Ee * 32]; // messages, tgt-sorted
__device__ __align__(16) __half d_hbuf_s[(long long)Bc * Ee * 32]; // messages, src-sorted
__device__ __align__(16) float d_h[Bc * Nn * HIDc];   // GRU hidden state
__device__ float d_xn[Bc * Nn];         // current node scalar
__device__ float d_ea[Ee];              // normalized edge attr (original order)
__device__ float d_stats[2];
__device__ int d_deg_t[Nn], d_deg_s[Nn];
__device__ int d_off_t[Nn + 1], d_off_s[Nn + 1];
__device__ int d_cnt_t[Nn], d_cnt_s[Nn];
__device__ int d_sslot_t[Ee];           // t-order slot -> s-order slot
__device__ int d_src_t[Ee], d_tgt_t[Ee];// node ids in t-order
__device__ float d_ea_t[Ee];            // edge attr in t-order
__device__ __align__(16) float2 d_wihT2[30 * 96];  // paired GRU input weights
__device__ __align__(16) float2 d_whhT2[64 * 96];  // paired GRU hidden weights
__device__ unsigned int d_bar_cnt;
__device__ volatile unsigned int d_bar_flag;

// ---------------- helpers ----------------
__device__ __forceinline__ float sigm(float x) {
    return __fdividef(1.0f, 1.0f + __expf(-x));
}
__device__ __forceinline__ float tanh_f(float x) {
    x = fminf(15.0f, fmaxf(-15.0f, x));
    float e = __expf(-2.0f * x);
    return __fdividef(1.0f - e, 1.0f + e);
}
__device__ __forceinline__ unsigned long long splat2(float x) {
    unsigned long long r;
    asm("mov.b64 %0, {%1, %1};" : "=l"(r) : "f"(x));
    return r;
}
__device__ __forceinline__ unsigned long long pack2(float lo, float hi) {
    unsigned long long r;
    asm("mov.b64 %0, {%1, %2};" : "=l"(r) : "f"(lo), "f"(hi));
    return r;
}
__device__ __forceinline__ void fma2(unsigned long long& d, unsigned long long a, unsigned long long b) {
    asm("fma.rn.f32x2 %0, %1, %2, %0;" : "+l"(d) : "l"(a), "l"(b));
}
__device__ __forceinline__ float2 unpack2(unsigned long long v) {
    float2 f;
    asm("mov.b64 {%0, %1}, %2;" : "=f"(f.x), "=f"(f.y) : "l"(v));
    return f;
}

// ---------------- grid barrier (monotonic flag, reset by separate kernel) ----
__device__ __forceinline__ void grid_bar(unsigned int phase, int nblocks) {
    __syncthreads();
    if (threadIdx.x == 0) {
        __threadfence();
        unsigned int old = atomicAdd(&d_bar_cnt, 1u);
        if (old == (unsigned)nblocks - 1u) {
            d_bar_cnt = 0u;
            __threadfence();
            d_bar_flag = phase;
        } else {
            while (d_bar_flag < phase) __nanosleep(60);
            __threadfence();
        }
    }
    __syncthreads();
}

__global__ void reset_bar_kernel() {
    if (threadIdx.x == 0) { d_bar_cnt = 0u; *(unsigned int*)&d_bar_flag = 0u; }
}

// ---------------- fused setup kernel (persistent, 132 blocks x 256) --------
static constexpr int SETUP_BLOCKS = 132;

__global__ void __launch_bounds__(256) setup_kernel(
    const float* __restrict__ t2m, const float* __restrict__ ea,
    const int* __restrict__ ei,
    const float* __restrict__ wih, const float* __restrict__ whh)
{
    const int g = blockIdx.x * 256 + threadIdx.x;
    const int NT = SETUP_BLOCKS * 256;
    __shared__ float ssum[256], ssq[256];

    // ---- P0: zero state, init xn, pack GRU weights ----
    if (g < 2) d_stats[g] = 0.f;
    for (int i = g; i < Nn; i += NT) { d_deg_t[i] = 0; d_deg_s[i] = 0; d_cnt_t[i] = 0; d_cnt_s[i] = 0; }
    for (int i = g; i < Bc * Nn; i += NT) {
        int b = i / Nn, n = i - b * Nn;
        d_xn[i] = t2m[((long long)b * HISTc + (HISTc - 1)) * Nn + n];
    }
    for (long long j = g; j < (long long)Bc * Nn * HIDc; j += NT) d_h[j] = 0.f;
    for (int i = g; i < 30 * 96; i += NT) {
        int k = i / 96, c = i - k * 96;
        int gg = c / 32, j = c - gg * 32;
        d_wihT2[i] = make_float2(wih[(gg * 64 + j) * 30 + k], wih[(gg * 64 + 32 + j) * 30 + k]);
    }
    for (int i = g; i < 64 * 96; i += NT) {
        int k = i / 96, c = i - k * 96;
        int gg = c / 32, j = c - gg * 32;
        d_whhT2[i] = make_float2(whh[(gg * 64 + j) * 64 + k], whh[(gg * 64 + 32 + j) * 64 + k]);
    }
    grid_bar(1, SETUP_BLOCKS);

    // ---- P1: edge-attr stats + degree histograms ----
    {
        float lsum = 0.f, lsq = 0.f;
        for (int i = g; i < Ee; i += NT) {
            float v = ea[i];
            lsum += v; lsq += v * v;
            atomicAdd(&d_deg_s[ei[i]], 1);
            atomicAdd(&d_deg_t[ei[Ee + i]], 1);
        }
        int t = threadIdx.x;
        ssum[t] = lsum; ssq[t] = lsq;
        __syncthreads();
        for (int s = 128; s > 0; s >>= 1) {
            if (t < s) { ssum[t] += ssum[t + s]; ssq[t] += ssq[t + s]; }
            __syncthreads();
        }
        if (t == 0) {
            atomicAdd(&d_stats[0], ssum[0]);
            atomicAdd(&d_stats[1], ssq[0]);
        }
    }
    grid_bar(2, SETUP_BLOCKS);

    // ---- P2: scans (blocks 0,1) + ea normalize (blocks >=2) ----
    if (blockIdx.x < 2) {
        int which = blockIdx.x;
        const int* deg = which ? d_deg_s : d_deg_t;
        int* off = which ? d_off_s : d_off_t;
        __shared__ int part[256];
        const int CH = (Nn + 255) / 256;
        int t = threadIdx.x;
        int s = 0;
        for (int i = 0; i < CH; i++) {
            int idx = t * CH + i;
            if (idx < Nn) s += deg[idx];
        }
        part[t] = s;
        __syncthreads();
        if (t == 0) {
            int run = 0;
            for (int i = 0; i < 256; i++) { int vv = part[i]; part[i] = run; run += vv; }
            off[Nn] = run;
        }
        __syncthreads();
        int run = part[t];
        for (int i = 0; i < CH; i++) {
            int idx = t * CH + i;
            if (idx < Nn) { off[idx] = run; run += deg[idx]; }
        }
    } else {
        float s = d_stats[0], sq = d_stats[1];
        float mean = s / (float)Ee;
        float var = (sq - s * s / (float)Ee) / (float)(Ee - 1);
        float inv = rsqrtf(var);
        int gg = (blockIdx.x - 2) * 256 + threadIdx.x;
        for (int i = gg; i < Ee; i += (SETUP_BLOCKS - 2) * 256)
            d_ea[i] = (ea[i] - mean) * inv;
    }
    grid_bar(3, SETUP_BLOCKS);

    // ---- P3: fill t-order tables + t->s slot map ----
    for (int e = g; e < Ee; e += NT) {
        int sn = ei[e], tn = ei[Ee + e];
        int ps = atomicAdd(&d_cnt_s[sn], 1);
        int sslot = d_off_s[sn] + ps;
        int pt = atomicAdd(&d_cnt_t[tn], 1);
        int tslot = d_off_t[tn] + pt;
        d_sslot_t[tslot] = sslot;
        d_src_t[tslot] = sn;
        d_tgt_t[tslot] = tn;
        d_ea_t[tslot] = d_ea[e];
    }
}

// ---------------- edge MLP kernel (FFMA2 + LDS.128 weights, fp16 dual output) ----------------
__global__ void __launch_bounds__(128) edge_kernel(
    const float* __restrict__ feat,
    const float* __restrict__ w1, const float* __restrict__ b1,
    const float* __restrict__ w2, const float* __restrict__ b2, int t)
{
    __shared__ __align__(16) float s_w1[35 * 32];
    __shared__ __align__(16) float s_b1[32];
    __shared__ __align__(16) float s_w2p[32 * 32];   // padded: 30 real + 2 zero per row
    __shared__ __align__(16) float s_b2[32];
    for (int i = threadIdx.x; i < 35 * 32; i += 128) s_w1[i] = w1[i];
    for (int i = threadIdx.x; i < 32 * 32; i += 128) {
        int k = i >> 5, j = i & 31;
        s_w2p[i] = (j < 30) ? w2[k * 30 + j] : 0.f;
    }
    if (threadIdx.x < 32) {
        s_b1[threadIdx.x] = b1[threadIdx.x];
        s_b2[threadIdx.x] = (threadIdx.x < 30) ? b2[threadIdx.x] : 0.f;
    }
    __syncthreads();

    int idx = blockIdx.x * 128 + threadIdx.x;
    int b = blockIdx.y;
    int sn = d_src_t[idx], tn = d_tgt_t[idx];
    int ss = d_sslot_t[idx];

    float in[35];
    in[0] = d_xn[b * Nn + sn];
    {
        const float4* fs = (const float4*)(feat + ((long long)(b * TT + HISTc + t) * Nn + sn) * 16);
        float4 f0 = fs[0], f1 = fs[1], f2 = fs[2], f3 = fs[3];
        in[1] = f0.x; in[2] = f0.y; in[3] = f0.z; in[4] = f0.w;
        in[5] = f1.x; in[6] = f1.y; in[7] = f1.z; in[8] = f1.w;
        in[9] = f2.x; in[10] = f2.y; in[11] = f2.z; in[12] = f2.w;
        in[13] = f3.x; in[14] = f3.y; in[15] = f3.z; in[16] = f3.w;
    }
    in[17] = d_xn[b * Nn + tn];
    {
        const float4* fs = (const float4*)(feat + ((long long)(b * TT + HISTc + t) * Nn + tn) * 16);
        float4 f0 = fs[0], f1 = fs[1], f2 = fs[2], f3 = fs[3];
        in[18] = f0.x; in[19] = f0.y; in[20] = f0.z; in[21] = f0.w;
        in[22] = f1.x; in[23] = f1.y; in[24] = f1.z; in[25] = f1.w;
        in[26] = f2.x; in[27] = f2.y; in[28] = f2.z; in[29] = f2.w;
        in[30] = f3.x; in[31] = f3.y; in[32] = f3.z; in[33] = f3.w;
    }
    in[34] = d_ea_t[idx];

    // ---- layer 1: 35 -> 32, LDS.128 weight pairs ----
    unsigned long long acc1[16];
    {
        const unsigned long long* bp = (const unsigned long long*)s_b1;
        #pragma unroll
        for (int j = 0; j < 16; j++) acc1[j] = bp[j];
    }
    {
        const ulonglong2* wp = (const ulonglong2*)s_w1;
        #pragma unroll
        for (int k = 0; k < 35; k++) {
            unsigned long long xk = splat2(in[k]);
            #pragma unroll
            for (int j = 0; j < 8; j++) {
                ulonglong2 wv = wp[k * 8 + j];
                fma2(acc1[2 * j], xk, wv.x);
                fma2(acc1[2 * j + 1], xk, wv.y);
            }
        }
    }
    float h1[32];
    #pragma unroll
    for (int j = 0; j < 16; j++) {
        float2 f = unpack2(acc1[j]);
        h1[2 * j] = sigm(f.x);
        h1[2 * j + 1] = sigm(f.y);
    }

    // ---- layer 2: 32 -> 30 (padded to 32), LDS.128 weight pairs ----
    unsigned long long acc2[16];
    {
        const unsigned long long* bp = (const unsigned long long*)s_b2;
        #pragma unroll
        for (int j = 0; j < 16; j++) acc2[j] = bp[j];
    }
    {
        const ulonglong2* wp = (const ulonglong2*)s_w2p;
        #pragma unroll
        for (int k = 0; k < 32; k++) {
            unsigned long long xk = splat2(h1[k]);
            #pragma unroll
            for (int j = 0; j < 8; j++) {
                ulonglong2 wv = wp[k * 8 + j];
                fma2(acc2[2 * j], xk, wv.x);
                fma2(acc2[2 * j + 1], xk, wv.y);
            }
        }
    }

    // ---- sigmoid + fp16 pack (channels 30,31 forced zero) ----
    uint32_t hp[16];
    #pragma unroll
    for (int j = 0; j < 15; j++) {
        float2 f = unpack2(acc2[j]);
        __half2 h = __floats2half2_rn(sigm(f.x), sigm(f.y));
        hp[j] = *(uint32_t*)&h;
    }
    hp[15] = 0u;

    const uint4* hpv = (const uint4*)hp;
    uint4* dt = (uint4*)(d_hbuf_t + ((long long)b * Ee + idx) * 32);
    uint4* ds = (uint4*)(d_hbuf_s + ((long long)b * Ee + ss) * 32);
    #pragma unroll
    for (int q = 0; q < 4; q++) dt[q] = hpv[q];
    #pragma unroll
    for (int q = 0; q < 4; q++) ds[q] = hpv[q];
}

// ---------------- persistent step2: 2 rows per warp ----------------
static constexpr int S2_BLOCKS = 296;
static constexpr int S2_WARPS  = 16;     // 512 threads
static constexpr int TASKS = Bc * Nn / 2;  // 40000

__global__ void __launch_bounds__(512) step2_kernel(
    const float* __restrict__ feat,
    const float* __restrict__ node_w, const float* __restrict__ node_b,
    const float* __restrict__ bih, const float* __restrict__ bhh,
    const float* __restrict__ fcw, const float* __restrict__ fcb,
    float* __restrict__ out, int t)
{
    extern __shared__ float dynw[];
    float2* s_wih2 = (float2*)dynw;                 // [30][96] pairs
    float2* s_whh2 = (float2*)(dynw + 30 * 96 * 2); // [64][96] pairs
    __shared__ __align__(16) float sx[S2_WARPS][2][32];   // agg per row
    __shared__ __align__(16) float sxin[S2_WARPS][2][32]; // xin per row
    __shared__ __align__(16) float sh[S2_WARPS][128];     // h, 2 rows linear
    __shared__ float s_nw[30 * 13], s_nb[16];

    for (int i = threadIdx.x; i < 30 * 96; i += 512) s_wih2[i] = d_wihT2[i];
    for (int i = threadIdx.x; i < 64 * 96; i += 512) s_whh2[i] = d_whhT2[i];
    for (int i = threadIdx.x; i < 30 * 13; i += 512) s_nw[i] = node_w[i];
    if (threadIdx.x < 13) s_nb[threadIdx.x] = node_b[threadIdx.x];
    __syncthreads();

    int lane = threadIdx.x & 31;
    int w = threadIdx.x >> 5;
    float* shp = sh[w];

    // hoisted per-lane constants
    unsigned long long bih_r = pack2(bih[lane],       bih[32 + lane]);
    unsigned long long bih_z = pack2(bih[64 + lane],  bih[96 + lane]);
    unsigned long long bih_n = pack2(bih[128 + lane], bih[160 + lane]);
    unsigned long long bhh_r = pack2(bhh[lane],       bhh[32 + lane]);
    unsigned long long bhh_z = pack2(bhh[64 + lane],  bhh[96 + lane]);
    unsigned long long bhh_n = pack2(bhh[128 + lane], bhh[160 + lane]);
    float fcw0 = fcw[lane], fcw1 = fcw[32 + lane];
    float fcb0 = fcb[0];

    for (int task = blockIdx.x * S2_WARPS + w; task < TASKS; task += S2_BLOCKS * S2_WARPS) {
        int row0 = task * 2;
        int b = row0 / Nn, n0 = row0 - b * Nn;   // both rows share b (Nn even)

        // --- gather agg for 2 rows ---
        #pragma unroll
        for (int r = 0; r < 2; r++) {
            int n = n0 + r;
            float acc = 0.f;
            int e0 = d_off_t[n], e1 = d_off_t[n + 1];
            const __half* p = d_hbuf_t + ((long long)b * Ee + e0) * 32 + lane;
            int cnt = e1 - e0;
            int i = 0;
            for (; i + 4 <= cnt; i += 4) {
                float v0 = __half2float(p[(long long)(i) * 32]);
                float v1 = __half2float(p[(long long)(i + 1) * 32]);
                float v2 = __half2float(p[(long long)(i + 2) * 32]);
                float v3 = __half2float(p[(long long)(i + 3) * 32]);
                acc += (v0 + v1) + (v2 + v3);
            }
            for (; i < cnt; i++) acc += __half2float(p[(long long)i * 32]);
            e0 = d_off_s[n]; e1 = d_off_s[n + 1];
            p = d_hbuf_s + ((long long)b * Ee + e0) * 32 + lane;
            cnt = e1 - e0;
            i = 0;
            for (; i + 4 <= cnt; i += 4) {
                float v0 = __half2float(p[(long long)(i) * 32]);
                float v1 = __half2float(p[(long long)(i + 1) * 32]);
                float v2 = __half2float(p[(long long)(i + 2) * 32]);
                float v3 = __half2float(p[(long long)(i + 3) * 32]);
                acc -= (v0 + v1) + (v2 + v3);
            }
            for (; i < cnt; i++) acc -= __half2float(p[(long long)i * 32]);
            sx[w][r][lane] = acc;
        }
        __syncwarp();

        // --- node MLP: both rows in one pass (26 active lanes) ---
        if (lane < 26) {
            int r = (lane >= 13) ? 1 : 0;
            int u = lane - 13 * r;
            float g = s_nb[u];
            #pragma unroll
            for (int k = 0; k < 30; k++) g = fmaf(sx[w][r][k], s_nw[k * 13 + u], g);
            sxin[w][r][u] = sigm(g);
        }
        if (lane < 2) sxin[w][lane][13] = d_xn[row0 + lane];
        #pragma unroll
        for (int r = 0; r < 2; r++) {
            if (lane < 16)
                sxin[w][r][14 + lane] = feat[((long long)(b * TT + HISTc + t) * Nn + n0 + r) * 16 + lane];
        }
        // load h (128 contiguous floats = 32 float4)
        ((float4*)shp)[lane] = ((const float4*)(d_h + (long long)row0 * 64))[lane];
        __syncwarp();

        // --- GRU: 2 rows share each weight load ---
        unsigned long long ar0 = bih_r, az0 = bih_z, an0 = bih_n;
        unsigned long long ar1 = bih_r, az1 = bih_z, an1 = bih_n;
        #pragma unroll
        for (int k = 0; k < 30; k++) {
            const unsigned long long* wr = (const unsigned long long*)(s_wih2 + k * 96);
            unsigned long long wR = wr[lane], wZ = wr[32 + lane], wN = wr[64 + lane];
            unsigned long long x0 = splat2(sxin[w][0][k]);
            unsigned long long x1 = splat2(sxin[w][1][k]);
            fma2(ar0, x0, wR); fma2(az0, x0, wZ); fma2(an0, x0, wN);
            fma2(ar1, x1, wR); fma2(az1, x1, wZ); fma2(an1, x1, wN);
        }
        unsigned long long gr0 = bhh_r, gz0 = bhh_z, gn0 = bhh_n;
        unsigned long long gr1 = bhh_r, gz1 = bhh_z, gn1 = bhh_n;
        #pragma unroll
        for (int k = 0; k < 64; k++) {
            const unsigned long long* wr = (const unsigned long long*)(s_whh2 + k * 96);
            unsigned long long wR = wr[lane], wZ = wr[32 + lane], wN = wr[64 + lane];
            unsigned long long h0 = splat2(shp[k]);
            unsigned long long h1 = splat2(shp[64 + k]);
            fma2(gr0, h0, wR); fma2(gz0, h0, wZ); fma2(gn0, h0, wN);
            fma2(gr1, h1, wR); fma2(gz1, h1, wZ); fma2(gn1, h1, wN);
        }

        // --- epilogue row 0 ---
        {
            float2 fa_r = unpack2(ar0), fa_z = unpack2(az0), fa_n = unpack2(an0);
            float2 fg_r = unpack2(gr0), fg_z = unpack2(gz0), fg_n = unpack2(gn0);
            float hold0 = shp[lane], hold1 = shp[32 + lane];
            float r0 = sigm(fa_r.x + fg_r.x), r1 = sigm(fa_r.y + fg_r.y);
            float z0 = sigm(fa_z.x + fg_z.x), z1 = sigm(fa_z.y + fg_z.y);
            float nn0 = tanh_f(fa_n.x + r0 * fg_n.x), nn1 = tanh_f(fa_n.y + r1 * fg_n.y);
            float hn0 = (1.f - z0) * nn0 + z0 * hold0;
            float hn1 = (1.f - z1) * nn1 + z1 * hold1;
            long long rw = (long long)row0 * 64;
            d_h[rw + lane] = hn0;
            d_h[rw + 32 + lane] = hn1;
            float o = hn0 * fcw0 + hn1 * fcw1;
            #pragma unroll
            for (int off = 16; off > 0; off >>= 1)
                o += __shfl_xor_sync(0xffffffffu, o, off);
            if (lane == 0) {
                float v = o + fcb0;
                d_xn[row0] = v;
                out[((long long)b * PREDc + t) * Nn + n0] = v;
            }
        }
        // --- epilogue row 1 ---
        {
            float2 fa_r = unpack2(ar1), fa_z = unpack2(az1), fa_n = unpack2(an1);
            float2 fg_r = unpack2(gr1), fg_z = unpack2(gz1), fg_n = unpack2(gn1);
            float hold0 = shp[64 + lane], hold1 = shp[96 + lane];
            float r0 = sigm(fa_r.x + fg_r.x), r1 = sigm(fa_r.y + fg_r.y);
            float z0 = sigm(fa_z.x + fg_z.x), z1 = sigm(fa_z.y + fg_z.y);
            float nn0 = tanh_f(fa_n.x + r0 * fg_n.x), nn1 = tanh_f(fa_n.y + r1 * fg_n.y);
            float hn0 = (1.f - z0) * nn0 + z0 * hold0;
            float hn1 = (1.f - z1) * nn1 + z1 * hold1;
            long long rw = (long long)(row0 + 1) * 64;
            d_h[rw + lane] = hn0;
            d_h[rw + 32 + lane] = hn1;
            float o = hn0 * fcw0 + hn1 * fcw1;
            #pragma unroll
            for (int off = 16; off > 0; off >>= 1)
                o += __shfl_xor_sync(0xffffffffu, o, off);
            if (lane == 0) {
                float v = o + fcb0;
                d_xn[row0 + 1] = v;
                out[((long long)b * PREDc + t) * Nn + n0 + 1] = v;
            }
        }
        __syncwarp();
    }
}

// ---------------- launcher ----------------
extern "C" void kernel_launch(void* const* d_in, const int* in_sizes, int n_in,
                              void* d_out, int out_size)
{
    const float* t2m  = (const float*)d_in[0];
    const float* feat = (const float*)d_in[1];
    const int*   ei   = (const int*)d_in[2];
    const float* ea   = (const float*)d_in[3];
    const float* w1   = (const float*)d_in[4];
    const float* b1   = (const float*)d_in[5];
    const float* w2   = (const float*)d_in[6];
    const float* b2   = (const float*)d_in[7];
    const float* nw   = (const float*)d_in[8];
    const float* nb   = (const float*)d_in[9];
    const float* wih  = (const float*)d_in[10];
    const float* whh  = (const float*)d_in[11];
    const float* bih  = (const float*)d_in[12];
    const float* bhh  = (const float*)d_in[13];
    const float* fcw  = (const float*)d_in[14];
    const float* fcb  = (const float*)d_in[15];
    float* out = (float*)d_out;

    const int smem2 = (30 * 96 + 64 * 96) * 2 * (int)sizeof(float);
    cudaFuncSetAttribute(step2_kernel, cudaFuncAttributeMaxDynamicSharedMemorySize, smem2);

    reset_bar_kernel<<<1, 32>>>();
    setup_kernel<<<SETUP_BLOCKS, 256>>>(t2m, ea, ei, wih, whh);

    dim3 egrid(Ee / 128, Bc);
    for (int t = 0; t < PREDc; t++) {
        edge_kernel<<<egrid, 128>>>(feat, w1, b1, w2, b2, t);
        step2_kernel<<<S2_BLOCKS, 512, smem2>>>(feat, nw, nb, bih, bhh, fcw, fcb, out, t);
    }
}

// round 7
// speedup vs baseline: 1.6284x; 1.4190x over previous
#include <cuda_runtime.h>
#include <cuda_fp16.h>
#include <math.h>
#include <stdint.h>

// Problem constants
static constexpr int Bc   = 8;
static constexpr int Nn   = 10000;
static constexpr int Ee   = 320000;
static constexpr int HISTc = 24;
static constexpr int PREDc = 12;
static constexpr int TT   = HISTc + PREDc;   // 36
static constexpr int HIDc = 64;

// ---------------- device scratch (static, no allocations) ----------------
__device__ __align__(16) __half d_hbuf_t[(long long)Bc * Ee * 32]; // messages, tgt-sorted
__device__ __align__(16) __half d_hbuf_s[(long long)Bc * Ee * 32]; // messages, src-sorted
__device__ __align__(16) __half d_us[Bc * Nn * 32];  // per-node W1s^T x + b1 (fp16)
__device__ __align__(16) __half d_ut[Bc * Nn * 32];  // per-node W1t^T x (fp16)
__device__ __align__(16) float d_h[Bc * Nn * HIDc];   // GRU hidden state
__device__ float d_xn[Bc * Nn];         // current node scalar
__device__ float d_ea[Ee];              // normalized edge attr (original order)
__device__ float d_stats[2];
__device__ int d_deg_t[Nn], d_deg_s[Nn];
__device__ int d_off_t[Nn + 1], d_off_s[Nn + 1];
__device__ int d_cnt_t[Nn], d_cnt_s[Nn];
__device__ int d_sslot_t[Ee];           // t-order slot -> s-order slot
__device__ int d_src_t[Ee], d_tgt_t[Ee];// node ids in t-order
__device__ float d_ea_t[Ee];            // edge attr in t-order
__device__ __align__(16) float2 d_wihT2[30 * 96];  // paired GRU input weights
__device__ __align__(16) float2 d_whhT2[64 * 96];  // paired GRU hidden weights
__device__ unsigned int d_bar_cnt;
__device__ volatile unsigned int d_bar_flag;

// ---------------- helpers ----------------
__device__ __forceinline__ float sigm(float x) {
    return __fdividef(1.0f, 1.0f + __expf(-x));
}
__device__ __forceinline__ float sigm_fast(float x) {
    float y = 0.5f * x;
    float tv;
    asm("tanh.approx.f32 %0, %1;" : "=f"(tv) : "f"(y));
    return fmaf(0.5f, tv, 0.5f);
}
__device__ __forceinline__ float tanh_f(float x) {
    x = fminf(15.0f, fmaxf(-15.0f, x));
    float e = __expf(-2.0f * x);
    return __fdividef(1.0f - e, 1.0f + e);
}
__device__ __forceinline__ unsigned long long splat2(float x) {
    unsigned long long r;
    asm("mov.b64 %0, {%1, %1};" : "=l"(r) : "f"(x));
    return r;
}
__device__ __forceinline__ unsigned long long pack2(float lo, float hi) {
    unsigned long long r;
    asm("mov.b64 %0, {%1, %2};" : "=l"(r) : "f"(lo), "f"(hi));
    return r;
}
__device__ __forceinline__ void fma2(unsigned long long& d, unsigned long long a, unsigned long long b) {
    asm("fma.rn.f32x2 %0, %1, %2, %0;" : "+l"(d) : "l"(a), "l"(b));
}
__device__ __forceinline__ float2 unpack2(unsigned long long v) {
    float2 f;
    asm("mov.b64 {%0, %1}, %2;" : "=f"(f.x), "=f"(f.y) : "l"(v));
    return f;
}

// ---------------- grid barrier (monotonic flag, reset by separate kernel) ----
__device__ __forceinline__ void grid_bar(unsigned int phase, int nblocks) {
    __syncthreads();
    if (threadIdx.x == 0) {
        __threadfence();
        unsigned int old = atomicAdd(&d_bar_cnt, 1u);
        if (old == (unsigned)nblocks - 1u) {
            d_bar_cnt = 0u;
            __threadfence();
            d_bar_flag = phase;
        } else {
            while (d_bar_flag < phase) __nanosleep(60);
            __threadfence();
        }
    }
    __syncthreads();
}

__global__ void reset_bar_kernel() {
    if (threadIdx.x == 0) { d_bar_cnt = 0u; *(unsigned int*)&d_bar_flag = 0u; }
}

// ---------------- fused setup kernel (persistent, 132 blocks x 256) --------
static constexpr int SETUP_BLOCKS = 132;

__global__ void __launch_bounds__(256) setup_kernel(
    const float* __restrict__ t2m, const float* __restrict__ ea,
    const int* __restrict__ ei,
    const float* __restrict__ wih, const float* __restrict__ whh)
{
    const int g = blockIdx.x * 256 + threadIdx.x;
    const int NT = SETUP_BLOCKS * 256;
    __shared__ float ssum[256], ssq[256];

    // ---- P0: zero state, init xn, pack GRU weights ----
    if (g < 2) d_stats[g] = 0.f;
    for (int i = g; i < Nn; i += NT) { d_deg_t[i] = 0; d_deg_s[i] = 0; d_cnt_t[i] = 0; d_cnt_s[i] = 0; }
    for (int i = g; i < Bc * Nn; i += NT) {
        int b = i / Nn, n = i - b * Nn;
        d_xn[i] = t2m[((long long)b * HISTc + (HISTc - 1)) * Nn + n];
    }
    for (long long j = g; j < (long long)Bc * Nn * HIDc; j += NT) d_h[j] = 0.f;
    for (int i = g; i < 30 * 96; i += NT) {
        int k = i / 96, c = i - k * 96;
        int gg = c / 32, j = c - gg * 32;
        d_wihT2[i] = make_float2(wih[(gg * 64 + j) * 30 + k], wih[(gg * 64 + 32 + j) * 30 + k]);
    }
    for (int i = g; i < 64 * 96; i += NT) {
        int k = i / 96, c = i - k * 96;
        int gg = c / 32, j = c - gg * 32;
        d_whhT2[i] = make_float2(whh[(gg * 64 + j) * 64 + k], whh[(gg * 64 + 32 + j) * 64 + k]);
    }
    grid_bar(1, SETUP_BLOCKS);

    // ---- P1: edge-attr stats + degree histograms ----
    {
        float lsum = 0.f, lsq = 0.f;
        for (int i = g; i < Ee; i += NT) {
            float v = ea[i];
            lsum += v; lsq += v * v;
            atomicAdd(&d_deg_s[ei[i]], 1);
            atomicAdd(&d_deg_t[ei[Ee + i]], 1);
        }
        int t = threadIdx.x;
        ssum[t] = lsum; ssq[t] = lsq;
        __syncthreads();
        for (int s = 128; s > 0; s >>= 1) {
            if (t < s) { ssum[t] += ssum[t + s]; ssq[t] += ssq[t + s]; }
            __syncthreads();
        }
        if (t == 0) {
            atomicAdd(&d_stats[0], ssum[0]);
            atomicAdd(&d_stats[1], ssq[0]);
        }
    }
    grid_bar(2, SETUP_BLOCKS);

    // ---- P2: scans (blocks 0,1) + ea normalize (blocks >=2) ----
    if (blockIdx.x < 2) {
        int which = blockIdx.x;
        const int* deg = which ? d_deg_s : d_deg_t;
        int* off = which ? d_off_s : d_off_t;
        __shared__ int part[256];
        const int CH = (Nn + 255) / 256;
        int t = threadIdx.x;
        int s = 0;
        for (int i = 0; i < CH; i++) {
            int idx = t * CH + i;
            if (idx < Nn) s += deg[idx];
        }
        part[t] = s;
        __syncthreads();
        if (t == 0) {
            int run = 0;
            for (int i = 0; i < 256; i++) { int vv = part[i]; part[i] = run; run += vv; }
            off[Nn] = run;
        }
        __syncthreads();
        int run = part[t];
        for (int i = 0; i < CH; i++) {
            int idx = t * CH + i;
            if (idx < Nn) { off[idx] = run; run += deg[idx]; }
        }
    } else {
        float s = d_stats[0], sq = d_stats[1];
        float mean = s / (float)Ee;
        float var = (sq - s * s / (float)Ee) / (float)(Ee - 1);
        float inv = rsqrtf(var);
        int gg = (blockIdx.x - 2) * 256 + threadIdx.x;
        for (int i = gg; i < Ee; i += (SETUP_BLOCKS - 2) * 256)
            d_ea[i] = (ea[i] - mean) * inv;
    }
    grid_bar(3, SETUP_BLOCKS);

    // ---- P3: fill t-order tables + t->s slot map ----
    for (int e = g; e < Ee; e += NT) {
        int sn = ei[e], tn = ei[Ee + e];
        int ps = atomicAdd(&d_cnt_s[sn], 1);
        int sslot = d_off_s[sn] + ps;
        int pt = atomicAdd(&d_cnt_t[tn], 1);
        int tslot = d_off_t[tn] + pt;
        d_sslot_t[tslot] = sslot;
        d_src_t[tslot] = sn;
        d_tgt_t[tslot] = tn;
        d_ea_t[tslot] = d_ea[e];
    }
}

// ---------------- per-node layer-1 precompute: u_s = W1s^T x + b1, u_t = W1t^T x
__global__ void __launch_bounds__(256) upre_kernel(
    const float* __restrict__ feat,
    const float* __restrict__ w1, const float* __restrict__ b1, int t)
{
    __shared__ float sw[34 * 32];
    __shared__ float sb[32];
    for (int i = threadIdx.x; i < 34 * 32; i += 256) sw[i] = w1[i];
    if (threadIdx.x < 32) sb[threadIdx.x] = b1[threadIdx.x];
    __syncthreads();

    int row = blockIdx.x * 256 + threadIdx.x;
    if (row >= Bc * Nn) return;
    int b = row / Nn, n = row - b * Nn;

    float x[17];
    x[0] = d_xn[row];
    {
        const float4* fs = (const float4*)(feat + ((long long)(b * TT + HISTc + t) * Nn + n) * 16);
        float4 f0 = fs[0], f1 = fs[1], f2 = fs[2], f3 = fs[3];
        x[1] = f0.x; x[2] = f0.y; x[3] = f0.z; x[4] = f0.w;
        x[5] = f1.x; x[6] = f1.y; x[7] = f1.z; x[8] = f1.w;
        x[9] = f2.x; x[10] = f2.y; x[11] = f2.z; x[12] = f2.w;
        x[13] = f3.x; x[14] = f3.y; x[15] = f3.z; x[16] = f3.w;
    }

    float us[32], ut[32];
    #pragma unroll
    for (int j = 0; j < 32; j++) { us[j] = sb[j]; ut[j] = 0.f; }
    #pragma unroll
    for (int k = 0; k < 17; k++) {
        float xk = x[k];
        const float* ws = sw + k * 32;
        const float* wt = sw + (17 + k) * 32;
        #pragma unroll
        for (int j = 0; j < 32; j++) {
            us[j] = fmaf(xk, ws[j], us[j]);
            ut[j] = fmaf(xk, wt[j], ut[j]);
        }
    }
    uint32_t ps[16], pt[16];
    #pragma unroll
    for (int j = 0; j < 16; j++) {
        __half2 hs = __floats2half2_rn(us[2 * j], us[2 * j + 1]);
        __half2 ht = __floats2half2_rn(ut[2 * j], ut[2 * j + 1]);
        ps[j] = *(uint32_t*)&hs;
        pt[j] = *(uint32_t*)&ht;
    }
    uint4* dus = (uint4*)(d_us + (long long)row * 32);
    uint4* dut = (uint4*)(d_ut + (long long)row * 32);
    const uint4* psv = (const uint4*)ps;
    const uint4* ptv = (const uint4*)pt;
    #pragma unroll
    for (int q = 0; q < 4; q++) { dus[q] = psv[q]; dut[q] = ptv[q]; }
}

// ---------------- edge kernel: layer1 from u_s/u_t, layer2 FFMA2, fp16 dual output
__global__ void __launch_bounds__(128) edge_kernel(
    const float* __restrict__ w1,
    const float* __restrict__ w2, const float* __restrict__ b2)
{
    __shared__ __align__(16) float s_w2p[32 * 32];   // padded: 30 real + 2 zero per row
    __shared__ __align__(16) float s_b2[32];
    __shared__ __align__(16) float s_wea[32];        // w1 row 34 (edge-attr weights)
    for (int i = threadIdx.x; i < 32 * 32; i += 128) {
        int k = i >> 5, j = i & 31;
        s_w2p[i] = (j < 30) ? w2[k * 30 + j] : 0.f;
    }
    if (threadIdx.x < 32) {
        s_b2[threadIdx.x] = (threadIdx.x < 30) ? b2[threadIdx.x] : 0.f;
        s_wea[threadIdx.x] = w1[34 * 32 + threadIdx.x];
    }
    __syncthreads();

    int idx = blockIdx.x * 128 + threadIdx.x;
    int b = blockIdx.y;
    int sn = d_src_t[idx], tn = d_tgt_t[idx];
    int ss = d_sslot_t[idx];
    float eav = d_ea_t[idx];

    const uint4* usv = (const uint4*)(d_us + ((long long)b * Nn + sn) * 32);
    const uint4* utv = (const uint4*)(d_ut + ((long long)b * Nn + tn) * 32);

    float h1[32];
    #pragma unroll
    for (int q = 0; q < 4; q++) {
        uint4 va = usv[q];
        uint4 vb = utv[q];
        const __half2* ha = (const __half2*)&va;
        const __half2* hb = (const __half2*)&vb;
        #pragma unroll
        for (int p = 0; p < 4; p++) {
            float2 fa = __half22float2(ha[p]);
            float2 fb = __half22float2(hb[p]);
            int c = q * 8 + p * 2;
            h1[c]     = sigm_fast(fmaf(eav, s_wea[c],     fa.x + fb.x));
            h1[c + 1] = sigm_fast(fmaf(eav, s_wea[c + 1], fa.y + fb.y));
        }
    }

    // ---- layer 2: 32 -> 30 (padded to 32), LDS.128 weight pairs ----
    unsigned long long acc2[16];
    {
        const unsigned long long* bp = (const unsigned long long*)s_b2;
        #pragma unroll
        for (int j = 0; j < 16; j++) acc2[j] = bp[j];
    }
    {
        const ulonglong2* wp = (const ulonglong2*)s_w2p;
        #pragma unroll
        for (int k = 0; k < 32; k++) {
            unsigned long long xk = splat2(h1[k]);
            #pragma unroll
            for (int j = 0; j < 8; j++) {
                ulonglong2 wv = wp[k * 8 + j];
                fma2(acc2[2 * j], xk, wv.x);
                fma2(acc2[2 * j + 1], xk, wv.y);
            }
        }
    }

    // ---- sigmoid + fp16 pack (channels 30,31 forced zero) ----
    uint32_t hp[16];
    #pragma unroll
    for (int j = 0; j < 15; j++) {
        float2 f = unpack2(acc2[j]);
        __half2 h = __floats2half2_rn(sigm_fast(f.x), sigm_fast(f.y));
        hp[j] = *(uint32_t*)&h;
    }
    hp[15] = 0u;

    const uint4* hpv = (const uint4*)hp;
    uint4* dt = (uint4*)(d_hbuf_t + ((long long)b * Ee + idx) * 32);
    uint4* ds = (uint4*)(d_hbuf_s + ((long long)b * Ee + ss) * 32);
    #pragma unroll
    for (int q = 0; q < 4; q++) dt[q] = hpv[q];
    #pragma unroll
    for (int q = 0; q < 4; q++) ds[q] = hpv[q];
}

// ---------------- persistent step2: 2 rows per warp, vectorized gather -----
static constexpr int S2_BLOCKS = 296;
static constexpr int S2_WARPS  = 16;     // 512 threads
static constexpr int TASKS = Bc * Nn / 2;  // 40000

__global__ void __launch_bounds__(512) step2_kernel(
    const float* __restrict__ feat,
    const float* __restrict__ node_w, const float* __restrict__ node_b,
    const float* __restrict__ bih, const float* __restrict__ bhh,
    const float* __restrict__ fcw, const float* __restrict__ fcb,
    float* __restrict__ out, int t)
{
    extern __shared__ float dynw[];
    float2* s_wih2 = (float2*)dynw;                 // [30][96] pairs
    float2* s_whh2 = (float2*)(dynw + 30 * 96 * 2); // [64][96] pairs
    __shared__ __align__(16) float sx[S2_WARPS][2][32];   // agg per row
    __shared__ __align__(16) float sxin[S2_WARPS][2][32]; // xin per row
    __shared__ __align__(16) float sh[S2_WARPS][128];     // h, 2 rows linear
    __shared__ float s_nw[30 * 13], s_nb[16];

    for (int i = threadIdx.x; i < 30 * 96; i += 512) s_wih2[i] = d_wihT2[i];
    for (int i = threadIdx.x; i < 64 * 96; i += 512) s_whh2[i] = d_whhT2[i];
    for (int i = threadIdx.x; i < 30 * 13; i += 512) s_nw[i] = node_w[i];
    if (threadIdx.x < 13) s_nb[threadIdx.x] = node_b[threadIdx.x];
    __syncthreads();

    int lane = threadIdx.x & 31;
    int w = threadIdx.x >> 5;
    float* shp = sh[w];
    int sub = lane >> 2;      // which edge in an 8-edge chunk
    int grp = lane & 3;       // channel group: channels 8*grp .. 8*grp+7

    // hoisted per-lane constants
    unsigned long long bih_r = pack2(bih[lane],       bih[32 + lane]);
    unsigned long long bih_z = pack2(bih[64 + lane],  bih[96 + lane]);
    unsigned long long bih_n = pack2(bih[128 + lane], bih[160 + lane]);
    unsigned long long bhh_r = pack2(bhh[lane],       bhh[32 + lane]);
    unsigned long long bhh_z = pack2(bhh[64 + lane],  bhh[96 + lane]);
    unsigned long long bhh_n = pack2(bhh[128 + lane], bhh[160 + lane]);
    float fcw0 = fcw[lane], fcw1 = fcw[32 + lane];
    float fcb0 = fcb[0];

    for (int task = blockIdx.x * S2_WARPS + w; task < TASKS; task += S2_BLOCKS * S2_WARPS) {
        int row0 = task * 2;
        int b = row0 / Nn, n0 = row0 - b * Nn;   // both rows share b (Nn even)

        // --- vectorized gather: 8 edges per LDG.128 per warp ---
        #pragma unroll
        for (int r = 0; r < 2; r++) {
            int n = n0 + r;
            float2 acc[4];
            #pragma unroll
            for (int p = 0; p < 4; p++) acc[p] = make_float2(0.f, 0.f);

            // + tgt stream
            {
                int e0 = d_off_t[n], e1 = d_off_t[n + 1];
                int cnt = e1 - e0;
                const uint4* p4 = (const uint4*)(d_hbuf_t + ((long long)b * Ee + e0) * 32);
                int full = cnt >> 3, tail = cnt & 7;
                for (int i = 0; i < full; i++) {
                    uint4 v = p4[i * 32 + lane];
                    const __half2* h = (const __half2*)&v;
                    #pragma unroll
                    for (int p = 0; p < 4; p++) {
                        float2 f = __half22float2(h[p]);
                        acc[p].x += f.x; acc[p].y += f.y;
                    }
                }
                if (sub < tail) {
                    uint4 v = p4[full * 32 + lane];
                    const __half2* h = (const __half2*)&v;
                    #pragma unroll
                    for (int p = 0; p < 4; p++) {
                        float2 f = __half22float2(h[p]);
                        acc[p].x += f.x; acc[p].y += f.y;
                    }
                }
            }
            // - src stream
            {
                int e0 = d_off_s[n], e1 = d_off_s[n + 1];
                int cnt = e1 - e0;
                const uint4* p4 = (const uint4*)(d_hbuf_s + ((long long)b * Ee + e0) * 32);
                int full = cnt >> 3, tail = cnt & 7;
                for (int i = 0; i < full; i++) {
                    uint4 v = p4[i * 32 + lane];
                    const __half2* h = (const __half2*)&v;
                    #pragma unroll
                    for (int p = 0; p < 4; p++) {
                        float2 f = __half22float2(h[p]);
                        acc[p].x -= f.x; acc[p].y -= f.y;
                    }
                }
                if (sub < tail) {
                    uint4 v = p4[full * 32 + lane];
                    const __half2* h = (const __half2*)&v;
                    #pragma unroll
                    for (int p = 0; p < 4; p++) {
                        float2 f = __half22float2(h[p]);
                        acc[p].x -= f.x; acc[p].y -= f.y;
                    }
                }
            }
            // butterfly over lanes sharing grp (strides 4,8,16)
            #pragma unroll
            for (int p = 0; p < 4; p++) {
                #pragma unroll
                for (int st = 4; st <= 16; st <<= 1) {
                    acc[p].x += __shfl_xor_sync(0xffffffffu, acc[p].x, st);
                    acc[p].y += __shfl_xor_sync(0xffffffffu, acc[p].y, st);
                }
            }
            if (lane < 4) {
                float2* sxf2 = (float2*)sx[w][r];
                #pragma unroll
                for (int p = 0; p < 4; p++) sxf2[lane * 4 + p] = acc[p];
            }
        }
        __syncwarp();

        // --- node MLP: both rows in one pass (26 active lanes) ---
        if (lane < 26) {
            int r = (lane >= 13) ? 1 : 0;
            int u = lane - 13 * r;
            float g = s_nb[u];
            #pragma unroll
            for (int k = 0; k < 30; k++) g = fmaf(sx[w][r][k], s_nw[k * 13 + u], g);
            sxin[w][r][u] = sigm(g);
        }
        if (lane < 2) sxin[w][lane][13] = d_xn[row0 + lane];
        #pragma unroll
        for (int r = 0; r < 2; r++) {
            if (lane < 16)
                sxin[w][r][14 + lane] = feat[((long long)(b * TT + HISTc + t) * Nn + n0 + r) * 16 + lane];
        }
        // load h (128 contiguous floats = 32 float4)
        ((float4*)shp)[lane] = ((const float4*)(d_h + (long long)row0 * 64))[lane];
        __syncwarp();

        // --- GRU: 2 rows share each weight load ---
        unsigned long long ar0 = bih_r, az0 = bih_z, an0 = bih_n;
        unsigned long long ar1 = bih_r, az1 = bih_z, an1 = bih_n;
        #pragma unroll
        for (int k = 0; k < 30; k++) {
            const unsigned long long* wr = (const unsigned long long*)(s_wih2 + k * 96);
            unsigned long long wR = wr[lane], wZ = wr[32 + lane], wN = wr[64 + lane];
            unsigned long long x0 = splat2(sxin[w][0][k]);
            unsigned long long x1 = splat2(sxin[w][1][k]);
            fma2(ar0, x0, wR); fma2(az0, x0, wZ); fma2(an0, x0, wN);
            fma2(ar1, x1, wR); fma2(az1, x1, wZ); fma2(an1, x1, wN);
        }
        unsigned long long gr0 = bhh_r, gz0 = bhh_z, gn0 = bhh_n;
        unsigned long long gr1 = bhh_r, gz1 = bhh_z, gn1 = bhh_n;
        #pragma unroll
        for (int k = 0; k < 64; k++) {
            const unsigned long long* wr = (const unsigned long long*)(s_whh2 + k * 96);
            unsigned long long wR = wr[lane], wZ = wr[32 + lane], wN = wr[64 + lane];
            unsigned long long h0 = splat2(shp[k]);
            unsigned long long h1 = splat2(shp[64 + k]);
            fma2(gr0, h0, wR); fma2(gz0, h0, wZ); fma2(gn0, h0, wN);
            fma2(gr1, h1, wR); fma2(gz1, h1, wZ); fma2(gn1, h1, wN);
        }

        // --- epilogue row 0 ---
        {
            float2 fa_r = unpack2(ar0), fa_z = unpack2(az0), fa_n = unpack2(an0);
            float2 fg_r = unpack2(gr0), fg_z = unpack2(gz0), fg_n = unpack2(gn0);
            float hold0 = shp[lane], hold1 = shp[32 + lane];
            float r0 = sigm(fa_r.x + fg_r.x), r1 = sigm(fa_r.y + fg_r.y);
            float z0 = sigm(fa_z.x + fg_z.x), z1 = sigm(fa_z.y + fg_z.y);
            float nn0 = tanh_f(fa_n.x + r0 * fg_n.x), nn1 = tanh_f(fa_n.y + r1 * fg_n.y);
            float hn0 = (1.f - z0) * nn0 + z0 * hold0;
            float hn1 = (1.f - z1) * nn1 + z1 * hold1;
            long long rw = (long long)row0 * 64;
            d_h[rw + lane] = hn0;
            d_h[rw + 32 + lane] = hn1;
            float o = hn0 * fcw0 + hn1 * fcw1;
            #pragma unroll
            for (int off = 16; off > 0; off >>= 1)
                o += __shfl_xor_sync(0xffffffffu, o, off);
            if (lane == 0) {
                float v = o + fcb0;
                d_xn[row0] = v;
                out[((long long)b * PREDc + t) * Nn + n0] = v;
            }
        }
        // --- epilogue row 1 ---
        {
            float2 fa_r = unpack2(ar1), fa_z = unpack2(az1), fa_n = unpack2(an1);
            float2 fg_r = unpack2(gr1), fg_z = unpack2(gz1), fg_n = unpack2(gn1);
            float hold0 = shp[64 + lane], hold1 = shp[96 + lane];
            float r0 = sigm(fa_r.x + fg_r.x), r1 = sigm(fa_r.y + fg_r.y);
            float z0 = sigm(fa_z.x + fg_z.x), z1 = sigm(fa_z.y + fg_z.y);
            float nn0 = tanh_f(fa_n.x + r0 * fg_n.x), nn1 = tanh_f(fa_n.y + r1 * fg_n.y);
            float hn0 = (1.f - z0) * nn0 + z0 * hold0;
            float hn1 = (1.f - z1) * nn1 + z1 * hold1;
            long long rw = (long long)(row0 + 1) * 64;
            d_h[rw + lane] = hn0;
            d_h[rw + 32 + lane] = hn1;
            float o = hn0 * fcw0 + hn1 * fcw1;
            #pragma unroll
            for (int off = 16; off > 0; off >>= 1)
                o += __shfl_xor_sync(0xffffffffu, o, off);
            if (lane == 0) {
                float v = o + fcb0;
                d_xn[row0 + 1] = v;
                out[((long long)b * PREDc + t) * Nn + n0 + 1] = v;
            }
        }
        __syncwarp();
    }
}

// ---------------- launcher ----------------
extern "C" void kernel_launch(void* const* d_in, const int* in_sizes, int n_in,
                              void* d_out, int out_size)
{
    const float* t2m  = (const float*)d_in[0];
    const float* feat = (const float*)d_in[1];
    const int*   ei   = (const int*)d_in[2];
    const float* ea   = (const float*)d_in[3];
    const float* w1   = (const float*)d_in[4];
    const float* b1   = (const float*)d_in[5];
    const float* w2   = (const float*)d_in[6];
    const float* b2   = (const float*)d_in[7];
    const float* nw   = (const float*)d_in[8];
    const float* nb   = (const float*)d_in[9];
    const float* wih  = (const float*)d_in[10];
    const float* whh  = (const float*)d_in[11];
    const float* bih  = (const float*)d_in[12];
    const float* bhh  = (const float*)d_in[13];
    const float* fcw  = (const float*)d_in[14];
    const float* fcb  = (const float*)d_in[15];
    float* out = (float*)d_out;

    const int smem2 = (30 * 96 + 64 * 96) * 2 * (int)sizeof(float);
    cudaFuncSetAttribute(step2_kernel, cudaFuncAttributeMaxDynamicSharedMemorySize, smem2);

    // launch-order padding: two extra (harmless) resets so ncu -s 5 -c 1
    // lands on edge_kernel (launch index 5) next capture.
    reset_bar_kernel<<<1, 32>>>();
    setup_kernel<<<SETUP_BLOCKS, 256>>>(t2m, ea, ei, wih, whh);
    reset_bar_kernel<<<1, 32>>>();
    reset_bar_kernel<<<1, 32>>>();

    dim3 egrid(Ee / 128, Bc);
    for (int t = 0; t < PREDc; t++) {
        upre_kernel<<<(Bc * Nn + 255) / 256, 256>>>(feat, w1, b1, t);
        edge_kernel<<<egrid, 128>>>(w1, w2, b2);
        step2_kernel<<<S2_BLOCKS, 512, smem2>>>(feat, nw, nb, bih, bhh, fcw, fcb, out, t);
    }
}